// round 11
// baseline (speedup 1.0000x reference)
#include <cuda_runtime.h>
#include <cuda_fp16.h>

#define DIMC 64
#define N_MAX 50048
#define E_MAX 800000
#define NEG_SLOPE 0.3f
#define BN_EPS 1e-5f

// Scratch (static __device__ per allocation rules)
__device__ __align__(16) float g_A[N_MAX * DIMC];    // feat @ (W1-W2)^T + b   (dst side, fp32)
__device__ __align__(16) __half g_B[N_MAX * DIMC];   // feat @ W2^T            (src side, fp16)
__device__ __align__(16) float g_wt[64 * 128];       // transformed weights, [k][c] layout
__device__ __align__(16) float g_sum[DIMC];
__device__ __align__(16) float g_sumsq[DIMC];
__device__ int g_cnt[N_MAX];
__device__ int g_cursor[N_MAX];  // init to FINAL start offset by k_scan; fill atomics on it
__device__ int g_off[N_MAX];     // FINAL start offset (global) after k_scan
__device__ int g_bsum[64];
__device__ volatile int g_syncS; // scan cross-block counter
__device__ volatile int g_syncE; // edge (stats->gather) cross-block counter
__device__ int g_srcs[E_MAX];

// Fused init: zero counters/stats/sync + build transformed weights
__global__ void k_init(const float* __restrict__ W, int n_nodes) {
    int i = blockIdx.x * blockDim.x + threadIdx.x;
    if (i < n_nodes) g_cnt[i] = 0;
    if (i < DIMC) { g_sum[i] = 0.f; g_sumsq[i] = 0.f; }
    if (i == 0) { g_syncS = 0; g_syncE = 0; }
    if (i < 64 * 128) {
        int k = i >> 7, c = i & 127;
        float v;
        if (c < 64) v = W[c * 128 + k] - W[c * 128 + 64 + k];
        else        v = W[(c - 64) * 128 + 64 + k];
        g_wt[i] = v;
    }
}

// Fused: transform (blocks [0, tblocks)) + in-degree count (remaining blocks).
__global__ __launch_bounds__(256) void k_transcount(const float* __restrict__ feat,
                                                    const float* __restrict__ b,
                                                    const int* __restrict__ ei,
                                                    int E, int n_nodes, int tblocks) {
    __shared__ __align__(16) float wt[64 * 128];   // 32 KB
    __shared__ float ft[64][64];                   // 16 KB
    if ((int)blockIdx.x >= tblocks) {
        // ---- count part ----
        int cb = blockIdx.x - tblocks;
        int cblocks = gridDim.x - tblocks;
        int stride = cblocks * 256;
        int gid = cb * 256 + threadIdx.x;
        const int* dstrow = ei + E;
        if ((E & 3) == 0) {
            int E4 = E >> 2;
            const int4* d4 = (const int4*)dstrow;
            for (int i = gid; i < E4; i += stride) {
                int4 v = d4[i];
                if ((unsigned)v.x < (unsigned)n_nodes) atomicAdd(&g_cnt[v.x], 1);
                if ((unsigned)v.y < (unsigned)n_nodes) atomicAdd(&g_cnt[v.y], 1);
                if ((unsigned)v.z < (unsigned)n_nodes) atomicAdd(&g_cnt[v.z], 1);
                if ((unsigned)v.w < (unsigned)n_nodes) atomicAdd(&g_cnt[v.w], 1);
            }
        } else {
            for (int e = gid; e < E; e += stride) {
                int dn = dstrow[e];
                if ((unsigned)dn < (unsigned)n_nodes) atomicAdd(&g_cnt[dn], 1);
            }
        }
        return;
    }
    // ---- transform part ----
    int tid = threadIdx.x;
    {
        const float4* src = (const float4*)g_wt;
        float4* dst = (float4*)wt;
        for (int i = tid; i < 64 * 128 / 4; i += 256) dst[i] = src[i];
    }
    int node0 = blockIdx.x * 64;
    {
        int k = tid & 63;
        for (int nn = tid >> 6; nn < 64; nn += 4) {
            int n = node0 + nn;
            ft[nn][k] = (n < n_nodes) ? feat[n * 64 + k] : 0.f;
        }
    }
    __syncthreads();
    int cg = tid & 31;
    int ng = tid >> 5;
    float a0[8], a1[8], a2[8], a3[8];
#pragma unroll
    for (int j = 0; j < 8; j++) { a0[j] = a1[j] = a2[j] = a3[j] = 0.f; }
    const float4* wt4 = (const float4*)wt;
#pragma unroll 4
    for (int k = 0; k < 64; k++) {
        float4 w = wt4[k * 32 + cg];
#pragma unroll
        for (int j = 0; j < 8; j++) {
            float f = ft[ng * 8 + j][k];
            a0[j] += f * w.x; a1[j] += f * w.y; a2[j] += f * w.z; a3[j] += f * w.w;
        }
    }
    int c0 = cg * 4;
#pragma unroll
    for (int j = 0; j < 8; j++) {
        int n = node0 + ng * 8 + j;
        if (n >= n_nodes) continue;
        if (c0 < 64) {
            float4 v = make_float4(a0[j] + b[c0], a1[j] + b[c0 + 1],
                                   a2[j] + b[c0 + 2], a3[j] + b[c0 + 3]);
            *(float4*)&g_A[n * 64 + c0] = v;
        } else {
            __half2 p0 = __floats2half2_rn(a0[j], a1[j]);
            __half2 p1 = __floats2half2_rn(a2[j], a3[j]);
            uint2 v;
            v.x = *reinterpret_cast<unsigned*>(&p0);
            v.y = *reinterpret_cast<unsigned*>(&p1);
            *(uint2*)&g_B[n * 64 + (c0 - 64)] = v;
        }
    }
}

// Single-launch global exclusive scan with cross-block sync (49 co-resident blocks).
// Writes FINAL start offsets into g_off AND g_cursor.
__global__ __launch_bounds__(1024) void k_scan(int n_nodes) {
    __shared__ int sh[1024];
    __shared__ int sh_boff;
    int t = threadIdx.x;
    int i = blockIdx.x * 1024 + t;
    int v = (i < n_nodes) ? g_cnt[i] : 0;
    sh[t] = v;
    __syncthreads();
    for (int d = 1; d < 1024; d <<= 1) {
        int x = (t >= d) ? sh[t - d] : 0;
        __syncthreads();
        sh[t] += x;
        __syncthreads();
    }
    int local_excl = sh[t] - v;
    if (t == 1023) g_bsum[blockIdx.x] = sh[1023];
    __threadfence();
    __syncthreads();
    if (t == 0) {
        atomicAdd((int*)&g_syncS, 1);
        while (g_syncS < (int)gridDim.x) { __nanosleep(100); }
    }
    __syncthreads();
    // warp-parallel prefix of block sums [0, blockIdx.x)
    if (t < 32) {
        int acc = 0;
        for (int bk = t; bk < (int)blockIdx.x; bk += 32) acc += __ldcg(&g_bsum[bk]);
#pragma unroll
        for (int o = 16; o > 0; o >>= 1) acc += __shfl_down_sync(0xffffffffu, acc, o);
        if (t == 0) sh_boff = acc;
    }
    __syncthreads();
    if (i < n_nodes) {
        int st = local_excl + sh_boff;
        g_off[i] = st;
        g_cursor[i] = st;
    }
}

// Bucket fill: single atomic per edge; launched as ONE full wave (1184 blocks).
__global__ __launch_bounds__(256) void k_fill(const int* __restrict__ ei, int E, int n_nodes) {
    int stride = gridDim.x * blockDim.x;
    int gid = blockIdx.x * blockDim.x + threadIdx.x;
    if ((E & 3) == 0) {
        int E4 = E >> 2;
        const int4* s4 = (const int4*)ei;
        const int4* d4 = (const int4*)(ei + E);
        for (int i = gid; i < E4; i += stride) {
            int4 ss = s4[i];
            int4 dd = d4[i];
            if ((unsigned)ss.x < (unsigned)n_nodes && (unsigned)dd.x < (unsigned)n_nodes) {
                int p = atomicAdd(&g_cursor[dd.x], 1);
                if ((unsigned)p < E_MAX) g_srcs[p] = ss.x;
            }
            if ((unsigned)ss.y < (unsigned)n_nodes && (unsigned)dd.y < (unsigned)n_nodes) {
                int p = atomicAdd(&g_cursor[dd.y], 1);
                if ((unsigned)p < E_MAX) g_srcs[p] = ss.y;
            }
            if ((unsigned)ss.z < (unsigned)n_nodes && (unsigned)dd.z < (unsigned)n_nodes) {
                int p = atomicAdd(&g_cursor[dd.z], 1);
                if ((unsigned)p < E_MAX) g_srcs[p] = ss.z;
            }
            if ((unsigned)ss.w < (unsigned)n_nodes && (unsigned)dd.w < (unsigned)n_nodes) {
                int p = atomicAdd(&g_cursor[dd.w], 1);
                if ((unsigned)p < E_MAX) g_srcs[p] = ss.w;
            }
        }
    } else {
        for (int e = gid; e < E; e += stride) {
            int sn = ei[e];
            int dn = ei[E + e];
            if ((unsigned)sn >= (unsigned)n_nodes || (unsigned)dn >= (unsigned)n_nodes) continue;
            int p = atomicAdd(&g_cursor[dn], 1);
            if ((unsigned)p < E_MAX) g_srcs[p] = sn;
        }
    }
}

// Merged stats + gather, one persistent launch (592 blocks = 4/SM, co-resident).
// Phase 1: BN stats over CSR (warp per node slice, unroll 8).
// Grid sync. Each thread derives scale/shift. Phase 2: gather + BN + LeakyReLU + mean.
__global__ __launch_bounds__(256) void k_edge(const float* __restrict__ gamma,
                                              const float* __restrict__ beta,
                                              float* __restrict__ out,
                                              int E, int n_nodes) {
    __shared__ float smS[64], smQ[64];
    int tid = threadIdx.x;
    if (tid < 64) { smS[tid] = 0.f; smQ[tid] = 0.f; }
    __syncthreads();
    int lane = tid & 31;
    int c = lane * 2;
    int gw = (blockIdx.x * blockDim.x + tid) >> 5;
    int nw = (gridDim.x * blockDim.x) >> 5;
    // ---- phase 1: stats ----
    {
        float s0 = 0.f, s1 = 0.f, q0 = 0.f, q1 = 0.f;
        for (int n = gw; n < n_nodes; n += nw) {
            float2 a = *(const float2*)&g_A[n * 64 + c];
            int off = g_off[n];
            int end = off + g_cnt[n];
            int i = off;
            for (; i + 7 < end; i += 8) {
                int e0 = g_srcs[i + 0], e1 = g_srcs[i + 1], e2 = g_srcs[i + 2], e3 = g_srcs[i + 3];
                int e4 = g_srcs[i + 4], e5 = g_srcs[i + 5], e6 = g_srcs[i + 6], e7 = g_srcs[i + 7];
                float2 b0 = __half22float2(*(const __half2*)&g_B[e0 * 64 + c]);
                float2 b1 = __half22float2(*(const __half2*)&g_B[e1 * 64 + c]);
                float2 b2 = __half22float2(*(const __half2*)&g_B[e2 * 64 + c]);
                float2 b3 = __half22float2(*(const __half2*)&g_B[e3 * 64 + c]);
                float2 b4 = __half22float2(*(const __half2*)&g_B[e4 * 64 + c]);
                float2 b5 = __half22float2(*(const __half2*)&g_B[e5 * 64 + c]);
                float2 b6 = __half22float2(*(const __half2*)&g_B[e6 * 64 + c]);
                float2 b7 = __half22float2(*(const __half2*)&g_B[e7 * 64 + c]);
                float h;
                h = a.x + b0.x; s0 += h; q0 += h * h;  h = a.y + b0.y; s1 += h; q1 += h * h;
                h = a.x + b1.x; s0 += h; q0 += h * h;  h = a.y + b1.y; s1 += h; q1 += h * h;
                h = a.x + b2.x; s0 += h; q0 += h * h;  h = a.y + b2.y; s1 += h; q1 += h * h;
                h = a.x + b3.x; s0 += h; q0 += h * h;  h = a.y + b3.y; s1 += h; q1 += h * h;
                h = a.x + b4.x; s0 += h; q0 += h * h;  h = a.y + b4.y; s1 += h; q1 += h * h;
                h = a.x + b5.x; s0 += h; q0 += h * h;  h = a.y + b5.y; s1 += h; q1 += h * h;
                h = a.x + b6.x; s0 += h; q0 += h * h;  h = a.y + b6.y; s1 += h; q1 += h * h;
                h = a.x + b7.x; s0 += h; q0 += h * h;  h = a.y + b7.y; s1 += h; q1 += h * h;
            }
            for (; i < end; i++) {
                int e0 = g_srcs[i];
                float2 b0 = __half22float2(*(const __half2*)&g_B[e0 * 64 + c]);
                float h;
                h = a.x + b0.x; s0 += h; q0 += h * h;
                h = a.y + b0.y; s1 += h; q1 += h * h;
            }
        }
        atomicAdd(&smS[c], s0); atomicAdd(&smS[c + 1], s1);
        atomicAdd(&smQ[c], q0); atomicAdd(&smQ[c + 1], q1);
        __syncthreads();
        if (tid < 64) { atomicAdd(&g_sum[tid], smS[tid]); atomicAdd(&g_sumsq[tid], smQ[tid]); }
        __threadfence();
        __syncthreads();
        if (tid == 0) {
            atomicAdd((int*)&g_syncE, 1);
            while (g_syncE < (int)gridDim.x) { __nanosleep(100); }
        }
        __syncthreads();
    }
    // ---- derive BN scale/shift for this lane's two channels ----
    float invE = 1.f / (float)E;
    float m0 = __ldcg(&g_sum[c]) * invE;
    float m1 = __ldcg(&g_sum[c + 1]) * invE;
    float v0 = __ldcg(&g_sumsq[c]) * invE - m0 * m0;
    float v1 = __ldcg(&g_sumsq[c + 1]) * invE - m1 * m1;
    float sc0 = gamma[c] * rsqrtf(v0 + BN_EPS);
    float sc1 = gamma[c + 1] * rsqrtf(v1 + BN_EPS);
    float sh0 = beta[c] - m0 * sc0;
    float sh1 = beta[c + 1] - m1 * sc1;
    // ---- phase 2: gather ----
    for (int n = gw; n < n_nodes; n += nw) {
        float2 a = *(const float2*)&g_A[n * 64 + c];
        int start = g_off[n];
        int deg = g_cnt[n];
        int end = start + deg;
        float acc0 = 0.f, acc1 = 0.f;
        int i = start;
        for (; i + 7 < end; i += 8) {
            int e0 = g_srcs[i + 0], e1 = g_srcs[i + 1], e2 = g_srcs[i + 2], e3 = g_srcs[i + 3];
            int e4 = g_srcs[i + 4], e5 = g_srcs[i + 5], e6 = g_srcs[i + 6], e7 = g_srcs[i + 7];
            float2 b0 = __half22float2(*(const __half2*)&g_B[e0 * 64 + c]);
            float2 b1 = __half22float2(*(const __half2*)&g_B[e1 * 64 + c]);
            float2 b2 = __half22float2(*(const __half2*)&g_B[e2 * 64 + c]);
            float2 b3 = __half22float2(*(const __half2*)&g_B[e3 * 64 + c]);
            float2 b4 = __half22float2(*(const __half2*)&g_B[e4 * 64 + c]);
            float2 b5 = __half22float2(*(const __half2*)&g_B[e5 * 64 + c]);
            float2 b6 = __half22float2(*(const __half2*)&g_B[e6 * 64 + c]);
            float2 b7 = __half22float2(*(const __half2*)&g_B[e7 * 64 + c]);
            float y;
            y = (a.x + b0.x) * sc0 + sh0; acc0 += fmaxf(y, NEG_SLOPE * y);
            y = (a.y + b0.y) * sc1 + sh1; acc1 += fmaxf(y, NEG_SLOPE * y);
            y = (a.x + b1.x) * sc0 + sh0; acc0 += fmaxf(y, NEG_SLOPE * y);
            y = (a.y + b1.y) * sc1 + sh1; acc1 += fmaxf(y, NEG_SLOPE * y);
            y = (a.x + b2.x) * sc0 + sh0; acc0 += fmaxf(y, NEG_SLOPE * y);
            y = (a.y + b2.y) * sc1 + sh1; acc1 += fmaxf(y, NEG_SLOPE * y);
            y = (a.x + b3.x) * sc0 + sh0; acc0 += fmaxf(y, NEG_SLOPE * y);
            y = (a.y + b3.y) * sc1 + sh1; acc1 += fmaxf(y, NEG_SLOPE * y);
            y = (a.x + b4.x) * sc0 + sh0; acc0 += fmaxf(y, NEG_SLOPE * y);
            y = (a.y + b4.y) * sc1 + sh1; acc1 += fmaxf(y, NEG_SLOPE * y);
            y = (a.x + b5.x) * sc0 + sh0; acc0 += fmaxf(y, NEG_SLOPE * y);
            y = (a.y + b5.y) * sc1 + sh1; acc1 += fmaxf(y, NEG_SLOPE * y);
            y = (a.x + b6.x) * sc0 + sh0; acc0 += fmaxf(y, NEG_SLOPE * y);
            y = (a.y + b6.y) * sc1 + sh1; acc1 += fmaxf(y, NEG_SLOPE * y);
            y = (a.x + b7.x) * sc0 + sh0; acc0 += fmaxf(y, NEG_SLOPE * y);
            y = (a.y + b7.y) * sc1 + sh1; acc1 += fmaxf(y, NEG_SLOPE * y);
        }
        for (; i < end; i++) {
            int e0 = g_srcs[i];
            float2 b0 = __half22float2(*(const __half2*)&g_B[e0 * 64 + c]);
            float y;
            y = (a.x + b0.x) * sc0 + sh0; acc0 += fmaxf(y, NEG_SLOPE * y);
            y = (a.y + b0.y) * sc1 + sh1; acc1 += fmaxf(y, NEG_SLOPE * y);
        }
        float inv = 1.f / fmaxf((float)deg, 1.f);
        *(float2*)&out[n * 64 + c] = make_float2(acc0 * inv, acc1 * inv);
    }
}

extern "C" void kernel_launch(void* const* d_in, const int* in_sizes, int n_in,
                              void* d_out, int out_size) {
    const float* feat = (const float*)d_in[0];
    const int* ei = (const int*)d_in[1];
    const float* W = (const float*)d_in[2];
    const float* b = (const float*)d_in[3];
    const float* gamma = (const float*)d_in[4];
    const float* beta = (const float*)d_in[5];
    float* out = (float*)d_out;

    int n_nodes = in_sizes[0] / DIMC;
    int E = in_sizes[1] / 2;
    if (n_nodes > N_MAX) n_nodes = N_MAX;
    if (E > E_MAX) E = E_MAX;

    int init_span = n_nodes > 64 * 128 ? n_nodes : 64 * 128;
    k_init<<<(init_span + 255) / 256, 256>>>(W, n_nodes);
    int tblocks = (n_nodes + 63) / 64;
    k_transcount<<<tblocks + 256, 256>>>(feat, b, ei, E, n_nodes, tblocks);
    int sblocks = (n_nodes + 1023) / 1024;
    k_scan<<<sblocks, 1024>>>(n_nodes);
    k_fill<<<1184, 256>>>(ei, E, n_nodes);
    k_edge<<<592, 256>>>(gamma, beta, out, E, n_nodes);
}

// round 12
// speedup vs baseline: 1.1020x; 1.1020x over previous
#include <cuda_runtime.h>
#include <cuda_fp16.h>

#define DIMC 64
#define N_MAX 50048
#define E_MAX 800000
#define NEG_SLOPE 0.3f
#define BN_EPS 1e-5f

// Scratch (static __device__ per allocation rules)
__device__ __align__(16) float g_A[N_MAX * DIMC];    // feat @ (W1-W2)^T + b   (dst side, fp32)
__device__ __align__(16) __half g_B[N_MAX * DIMC];   // feat @ W2^T            (src side, fp16)
__device__ __align__(16) float g_wt[64 * 128];       // transformed weights, [k][c] layout
__device__ __align__(16) float g_sum[DIMC];
__device__ __align__(16) float g_sumsq[DIMC];
__device__ __align__(16) float g_scale[DIMC];
__device__ __align__(16) float g_shift[DIMC];
__device__ int g_cnt[N_MAX];
__device__ int g_cursor[N_MAX];  // init to FINAL start offset by k_scan; fill atomics on it
__device__ int g_off[N_MAX];     // FINAL start offset (global) after k_scan
__device__ int g_bsum[64];
__device__ int g_done;           // stats done-counter
__device__ volatile int g_syncS; // scan cross-block counter
__device__ int g_srcs[E_MAX];

// Fused init: zero counters/stats/sync + build transformed weights
__global__ void k_init(const float* __restrict__ W, int n_nodes) {
    int i = blockIdx.x * blockDim.x + threadIdx.x;
    if (i < n_nodes) g_cnt[i] = 0;
    if (i < DIMC) { g_sum[i] = 0.f; g_sumsq[i] = 0.f; }
    if (i == 0) { g_syncS = 0; g_done = 0; }
    if (i < 64 * 128) {
        int k = i >> 7, c = i & 127;
        float v;
        if (c < 64) v = W[c * 128 + k] - W[c * 128 + 64 + k];
        else        v = W[(c - 64) * 128 + 64 + k];
        g_wt[i] = v;
    }
}

// Fused: transform (blocks [0, tblocks)) + in-degree count (remaining blocks).
// Transform inner loop uses packed fma.rn.f32x2 (2 FMA per FMA-pipe issue).
__global__ __launch_bounds__(256) void k_transcount(const float* __restrict__ feat,
                                                    const float* __restrict__ b,
                                                    const int* __restrict__ ei,
                                                    int E, int n_nodes, int tblocks) {
    __shared__ __align__(16) float wt[64 * 128];   // 32 KB
    __shared__ float ft[64][64];                   // 16 KB
    if ((int)blockIdx.x >= tblocks) {
        // ---- count part ----
        int cb = blockIdx.x - tblocks;
        int cblocks = gridDim.x - tblocks;
        int stride = cblocks * 256;
        int gid = cb * 256 + threadIdx.x;
        const int* dstrow = ei + E;
        if ((E & 3) == 0) {
            int E4 = E >> 2;
            const int4* d4 = (const int4*)dstrow;
            for (int i = gid; i < E4; i += stride) {
                int4 v = d4[i];
                if ((unsigned)v.x < (unsigned)n_nodes) atomicAdd(&g_cnt[v.x], 1);
                if ((unsigned)v.y < (unsigned)n_nodes) atomicAdd(&g_cnt[v.y], 1);
                if ((unsigned)v.z < (unsigned)n_nodes) atomicAdd(&g_cnt[v.z], 1);
                if ((unsigned)v.w < (unsigned)n_nodes) atomicAdd(&g_cnt[v.w], 1);
            }
        } else {
            for (int e = gid; e < E; e += stride) {
                int dn = dstrow[e];
                if ((unsigned)dn < (unsigned)n_nodes) atomicAdd(&g_cnt[dn], 1);
            }
        }
        return;
    }
    // ---- transform part ----
    int tid = threadIdx.x;
    {
        const float4* src = (const float4*)g_wt;
        float4* dst = (float4*)wt;
        for (int i = tid; i < 64 * 128 / 4; i += 256) dst[i] = src[i];
    }
    int node0 = blockIdx.x * 64;
    {
        int k = tid & 63;
        for (int nn = tid >> 6; nn < 64; nn += 4) {
            int n = node0 + nn;
            ft[nn][k] = (n < n_nodes) ? feat[n * 64 + k] : 0.f;
        }
    }
    __syncthreads();
    int cg = tid & 31;   // cols cg*4 .. cg*4+3
    int ng = tid >> 5;   // nodes ng*8 .. ng*8+7
    unsigned long long acc01[8], acc23[8];
#pragma unroll
    for (int j = 0; j < 8; j++) { acc01[j] = 0ull; acc23[j] = 0ull; }
    const float4* wt4 = (const float4*)wt;
#pragma unroll 4
    for (int k = 0; k < 64; k++) {
        float4 w = wt4[k * 32 + cg];
        unsigned long long wxy, wzw;
        asm("mov.b64 %0, {%1, %2};" : "=l"(wxy) : "f"(w.x), "f"(w.y));
        asm("mov.b64 %0, {%1, %2};" : "=l"(wzw) : "f"(w.z), "f"(w.w));
#pragma unroll
        for (int j = 0; j < 8; j++) {
            float f = ft[ng * 8 + j][k];
            unsigned long long ff;
            asm("mov.b64 %0, {%1, %1};" : "=l"(ff) : "f"(f));
            asm("fma.rn.f32x2 %0, %1, %2, %0;" : "+l"(acc01[j]) : "l"(ff), "l"(wxy));
            asm("fma.rn.f32x2 %0, %1, %2, %0;" : "+l"(acc23[j]) : "l"(ff), "l"(wzw));
        }
    }
    int c0 = cg * 4;
#pragma unroll
    for (int j = 0; j < 8; j++) {
        int n = node0 + ng * 8 + j;
        if (n >= n_nodes) continue;
        float a0, a1, a2, a3;
        asm("mov.b64 {%0, %1}, %2;" : "=f"(a0), "=f"(a1) : "l"(acc01[j]));
        asm("mov.b64 {%0, %1}, %2;" : "=f"(a2), "=f"(a3) : "l"(acc23[j]));
        if (c0 < 64) {
            float4 v = make_float4(a0 + b[c0], a1 + b[c0 + 1],
                                   a2 + b[c0 + 2], a3 + b[c0 + 3]);
            *(float4*)&g_A[n * 64 + c0] = v;
        } else {
            __half2 p0 = __floats2half2_rn(a0, a1);
            __half2 p1 = __floats2half2_rn(a2, a3);
            uint2 v;
            v.x = *reinterpret_cast<unsigned*>(&p0);
            v.y = *reinterpret_cast<unsigned*>(&p1);
            *(uint2*)&g_B[n * 64 + (c0 - 64)] = v;
        }
    }
}

// Single-launch global exclusive scan (warp-shuffle based) with cross-block sync.
// Writes FINAL start offsets into g_off AND g_cursor.
__global__ __launch_bounds__(1024) void k_scan(int n_nodes) {
    __shared__ int warp_sums[32];
    __shared__ int sh_boff;
    int t = threadIdx.x;
    int lane = t & 31, wid = t >> 5;
    int i = blockIdx.x * 1024 + t;
    int v = (i < n_nodes) ? g_cnt[i] : 0;
    // warp inclusive scan
    int x = v;
#pragma unroll
    for (int o = 1; o < 32; o <<= 1) {
        int y = __shfl_up_sync(0xffffffffu, x, o);
        if (lane >= o) x += y;
    }
    if (lane == 31) warp_sums[wid] = x;
    __syncthreads();
    if (wid == 0) {
        int s = warp_sums[lane];
#pragma unroll
        for (int o = 1; o < 32; o <<= 1) {
            int y = __shfl_up_sync(0xffffffffu, s, o);
            if (lane >= o) s += y;
        }
        warp_sums[lane] = s;
    }
    __syncthreads();
    int warp_off = (wid > 0) ? warp_sums[wid - 1] : 0;
    int incl = x + warp_off;
    int local_excl = incl - v;
    if (t == 1023) g_bsum[blockIdx.x] = incl;
    __threadfence();
    __syncthreads();
    if (t == 0) {
        atomicAdd((int*)&g_syncS, 1);
        while (g_syncS < (int)gridDim.x) { __nanosleep(100); }
    }
    __syncthreads();
    // warp-parallel prefix of block sums [0, blockIdx.x)
    if (t < 32) {
        int acc = 0;
        for (int bk = t; bk < (int)blockIdx.x; bk += 32) acc += __ldcg(&g_bsum[bk]);
#pragma unroll
        for (int o = 16; o > 0; o >>= 1) acc += __shfl_down_sync(0xffffffffu, acc, o);
        if (t == 0) sh_boff = acc;
    }
    __syncthreads();
    if (i < n_nodes) {
        int st = local_excl + sh_boff;
        g_off[i] = st;
        g_cursor[i] = st;
    }
}

// Bucket fill: single atomic per edge (cursor pre-seeded with final start offset).
__global__ __launch_bounds__(256) void k_fill(const int* __restrict__ ei, int E, int n_nodes) {
    int stride = gridDim.x * blockDim.x;
    int gid = blockIdx.x * blockDim.x + threadIdx.x;
    if ((E & 3) == 0) {
        int E4 = E >> 2;
        const int4* s4 = (const int4*)ei;
        const int4* d4 = (const int4*)(ei + E);
        for (int i = gid; i < E4; i += stride) {
            int4 ss = s4[i];
            int4 dd = d4[i];
            if ((unsigned)ss.x < (unsigned)n_nodes && (unsigned)dd.x < (unsigned)n_nodes) {
                int p = atomicAdd(&g_cursor[dd.x], 1);
                if ((unsigned)p < E_MAX) g_srcs[p] = ss.x;
            }
            if ((unsigned)ss.y < (unsigned)n_nodes && (unsigned)dd.y < (unsigned)n_nodes) {
                int p = atomicAdd(&g_cursor[dd.y], 1);
                if ((unsigned)p < E_MAX) g_srcs[p] = ss.y;
            }
            if ((unsigned)ss.z < (unsigned)n_nodes && (unsigned)dd.z < (unsigned)n_nodes) {
                int p = atomicAdd(&g_cursor[dd.z], 1);
                if ((unsigned)p < E_MAX) g_srcs[p] = ss.z;
            }
            if ((unsigned)ss.w < (unsigned)n_nodes && (unsigned)dd.w < (unsigned)n_nodes) {
                int p = atomicAdd(&g_cursor[dd.w], 1);
                if ((unsigned)p < E_MAX) g_srcs[p] = ss.w;
            }
        }
    } else {
        for (int e = gid; e < E; e += stride) {
            int sn = ei[e];
            int dn = ei[E + e];
            if ((unsigned)sn >= (unsigned)n_nodes || (unsigned)dn >= (unsigned)n_nodes) continue;
            int p = atomicAdd(&g_cursor[dn], 1);
            if ((unsigned)p < E_MAX) g_srcs[p] = sn;
        }
    }
}

// Node-centric BN stats over CSR: warp per node slice, lane covers 2 channels (half2 B).
// Unroll 8 for MLP. Fused BN finalization via done-counter.
__global__ __launch_bounds__(256) void k_stats(const float* __restrict__ gamma,
                                               const float* __restrict__ beta,
                                               int E, int n_nodes) {
    __shared__ float smS[64], smQ[64];
    __shared__ int sh_last;
    int tid = threadIdx.x;
    if (tid < 64) { smS[tid] = 0.f; smQ[tid] = 0.f; }
    __syncthreads();
    int lane = tid & 31;
    int c = lane * 2;
    int gw = (blockIdx.x * blockDim.x + tid) >> 5;
    int nw = (gridDim.x * blockDim.x) >> 5;
    float s0 = 0.f, s1 = 0.f, q0 = 0.f, q1 = 0.f;
    for (int n = gw; n < n_nodes; n += nw) {
        float2 a = *(const float2*)&g_A[n * 64 + c];
        int off = g_off[n];
        int end = off + g_cnt[n];
        int i = off;
        for (; i + 7 < end; i += 8) {
            int e0 = g_srcs[i + 0], e1 = g_srcs[i + 1], e2 = g_srcs[i + 2], e3 = g_srcs[i + 3];
            int e4 = g_srcs[i + 4], e5 = g_srcs[i + 5], e6 = g_srcs[i + 6], e7 = g_srcs[i + 7];
            float2 b0 = __half22float2(*(const __half2*)&g_B[e0 * 64 + c]);
            float2 b1 = __half22float2(*(const __half2*)&g_B[e1 * 64 + c]);
            float2 b2 = __half22float2(*(const __half2*)&g_B[e2 * 64 + c]);
            float2 b3 = __half22float2(*(const __half2*)&g_B[e3 * 64 + c]);
            float2 b4 = __half22float2(*(const __half2*)&g_B[e4 * 64 + c]);
            float2 b5 = __half22float2(*(const __half2*)&g_B[e5 * 64 + c]);
            float2 b6 = __half22float2(*(const __half2*)&g_B[e6 * 64 + c]);
            float2 b7 = __half22float2(*(const __half2*)&g_B[e7 * 64 + c]);
            float h;
            h = a.x + b0.x; s0 += h; q0 += h * h;  h = a.y + b0.y; s1 += h; q1 += h * h;
            h = a.x + b1.x; s0 += h; q0 += h * h;  h = a.y + b1.y; s1 += h; q1 += h * h;
            h = a.x + b2.x; s0 += h; q0 += h * h;  h = a.y + b2.y; s1 += h; q1 += h * h;
            h = a.x + b3.x; s0 += h; q0 += h * h;  h = a.y + b3.y; s1 += h; q1 += h * h;
            h = a.x + b4.x; s0 += h; q0 += h * h;  h = a.y + b4.y; s1 += h; q1 += h * h;
            h = a.x + b5.x; s0 += h; q0 += h * h;  h = a.y + b5.y; s1 += h; q1 += h * h;
            h = a.x + b6.x; s0 += h; q0 += h * h;  h = a.y + b6.y; s1 += h; q1 += h * h;
            h = a.x + b7.x; s0 += h; q0 += h * h;  h = a.y + b7.y; s1 += h; q1 += h * h;
        }
        for (; i < end; i++) {
            int e0 = g_srcs[i];
            float2 b0 = __half22float2(*(const __half2*)&g_B[e0 * 64 + c]);
            float h;
            h = a.x + b0.x; s0 += h; q0 += h * h;
            h = a.y + b0.y; s1 += h; q1 += h * h;
        }
    }
    atomicAdd(&smS[c], s0); atomicAdd(&smS[c + 1], s1);
    atomicAdd(&smQ[c], q0); atomicAdd(&smQ[c + 1], q1);
    __syncthreads();
    if (tid < 64) { atomicAdd(&g_sum[tid], smS[tid]); atomicAdd(&g_sumsq[tid], smQ[tid]); }
    __threadfence();
    if (tid == 0) {
        int prev = atomicAdd(&g_done, 1);
        sh_last = (prev == (int)gridDim.x - 1) ? 1 : 0;
    }
    __syncthreads();
    if (sh_last && tid < 64) {
        float invE = 1.f / (float)E;
        float mean = __ldcg(&g_sum[tid]) * invE;
        float var = __ldcg(&g_sumsq[tid]) * invE - mean * mean;
        float sc = gamma[tid] * rsqrtf(var + BN_EPS);
        g_scale[tid] = sc;
        g_shift[tid] = beta[tid] - mean * sc;
    }
}

// Node-centric gather: one warp per node; unroll 8; fuses BN affine, LeakyReLU, mean divide.
__global__ __launch_bounds__(256) void k_gather(float* __restrict__ out, int n_nodes) {
    int lane = threadIdx.x & 31;
    int n = (blockIdx.x * blockDim.x + threadIdx.x) >> 5;
    if (n >= n_nodes) return;
    int c = lane * 2;
    float2 a = *(const float2*)&g_A[n * 64 + c];
    float sc0 = g_scale[c], sc1 = g_scale[c + 1];
    float sh0 = g_shift[c], sh1 = g_shift[c + 1];
    int start = g_off[n];
    int deg = g_cnt[n];
    int end = start + deg;
    float acc0 = 0.f, acc1 = 0.f;
    int i = start;
    for (; i + 7 < end; i += 8) {
        int e0 = g_srcs[i + 0], e1 = g_srcs[i + 1], e2 = g_srcs[i + 2], e3 = g_srcs[i + 3];
        int e4 = g_srcs[i + 4], e5 = g_srcs[i + 5], e6 = g_srcs[i + 6], e7 = g_srcs[i + 7];
        float2 b0 = __half22float2(*(const __half2*)&g_B[e0 * 64 + c]);
        float2 b1 = __half22float2(*(const __half2*)&g_B[e1 * 64 + c]);
        float2 b2 = __half22float2(*(const __half2*)&g_B[e2 * 64 + c]);
        float2 b3 = __half22float2(*(const __half2*)&g_B[e3 * 64 + c]);
        float2 b4 = __half22float2(*(const __half2*)&g_B[e4 * 64 + c]);
        float2 b5 = __half22float2(*(const __half2*)&g_B[e5 * 64 + c]);
        float2 b6 = __half22float2(*(const __half2*)&g_B[e6 * 64 + c]);
        float2 b7 = __half22float2(*(const __half2*)&g_B[e7 * 64 + c]);
        float y;
        y = (a.x + b0.x) * sc0 + sh0; acc0 += fmaxf(y, NEG_SLOPE * y);
        y = (a.y + b0.y) * sc1 + sh1; acc1 += fmaxf(y, NEG_SLOPE * y);
        y = (a.x + b1.x) * sc0 + sh0; acc0 += fmaxf(y, NEG_SLOPE * y);
        y = (a.y + b1.y) * sc1 + sh1; acc1 += fmaxf(y, NEG_SLOPE * y);
        y = (a.x + b2.x) * sc0 + sh0; acc0 += fmaxf(y, NEG_SLOPE * y);
        y = (a.y + b2.y) * sc1 + sh1; acc1 += fmaxf(y, NEG_SLOPE * y);
        y = (a.x + b3.x) * sc0 + sh0; acc0 += fmaxf(y, NEG_SLOPE * y);
        y = (a.y + b3.y) * sc1 + sh1; acc1 += fmaxf(y, NEG_SLOPE * y);
        y = (a.x + b4.x) * sc0 + sh0; acc0 += fmaxf(y, NEG_SLOPE * y);
        y = (a.y + b4.y) * sc1 + sh1; acc1 += fmaxf(y, NEG_SLOPE * y);
        y = (a.x + b5.x) * sc0 + sh0; acc0 += fmaxf(y, NEG_SLOPE * y);
        y = (a.y + b5.y) * sc1 + sh1; acc1 += fmaxf(y, NEG_SLOPE * y);
        y = (a.x + b6.x) * sc0 + sh0; acc0 += fmaxf(y, NEG_SLOPE * y);
        y = (a.y + b6.y) * sc1 + sh1; acc1 += fmaxf(y, NEG_SLOPE * y);
        y = (a.x + b7.x) * sc0 + sh0; acc0 += fmaxf(y, NEG_SLOPE * y);
        y = (a.y + b7.y) * sc1 + sh1; acc1 += fmaxf(y, NEG_SLOPE * y);
    }
    for (; i < end; i++) {
        int e0 = g_srcs[i];
        float2 b0 = __half22float2(*(const __half2*)&g_B[e0 * 64 + c]);
        float y;
        y = (a.x + b0.x) * sc0 + sh0; acc0 += fmaxf(y, NEG_SLOPE * y);
        y = (a.y + b0.y) * sc1 + sh1; acc1 += fmaxf(y, NEG_SLOPE * y);
    }
    float inv = 1.f / fmaxf((float)deg, 1.f);
    *(float2*)&out[n * 64 + c] = make_float2(acc0 * inv, acc1 * inv);
}

extern "C" void kernel_launch(void* const* d_in, const int* in_sizes, int n_in,
                              void* d_out, int out_size) {
    const float* feat = (const float*)d_in[0];
    const int* ei = (const int*)d_in[1];
    const float* W = (const float*)d_in[2];
    const float* b = (const float*)d_in[3];
    const float* gamma = (const float*)d_in[4];
    const float* beta = (const float*)d_in[5];
    float* out = (float*)d_out;

    int n_nodes = in_sizes[0] / DIMC;
    int E = in_sizes[1] / 2;
    if (n_nodes > N_MAX) n_nodes = N_MAX;
    if (E > E_MAX) E = E_MAX;

    int init_span = n_nodes > 64 * 128 ? n_nodes : 64 * 128;
    k_init<<<(init_span + 255) / 256, 256>>>(W, n_nodes);
    int tblocks = (n_nodes + 63) / 64;
    k_transcount<<<tblocks + 256, 256>>>(feat, b, ei, E, n_nodes, tblocks);
    int sblocks = (n_nodes + 1023) / 1024;
    k_scan<<<sblocks, 1024>>>(n_nodes);
    k_fill<<<1024, 256>>>(ei, E, n_nodes);
    k_stats<<<592, 256>>>(gamma, beta, E, n_nodes);
    k_gather<<<(n_nodes * 32 + 255) / 256, 256>>>(out, n_nodes);
}